// round 15
// baseline (speedup 1.0000x reference)
#include <cuda_runtime.h>
#include <cuda_bf16.h>
#include <math.h>
#include <cstdint>

#define NN 50000
#define SEQL 52
#define FIN 16
#define HD 128
#define H3 384
#define NE 800000
#define ET (NE + NN)
#define NEG 0.2f
#define MBLOCKS ((NN + 127) / 128)

// ---------------- static scratch ----------------
static __device__ float d_xp[(size_t)NN * HD];
static __device__ float d_as[NN];
static __device__ float d_ad[NN];
static __device__ unsigned short d_sph[(size_t)NN * HD];   // spatial hi bf16
static __device__ unsigned short d_spl[(size_t)NN * HD];   // spatial lo bf16
static __device__ float d_gi[(size_t)NN * H3];
static __device__ float d_gh[(size_t)NN * H3];
static __device__ float d_h[(size_t)NN * HD];
static __device__ unsigned short d_hh[(size_t)NN * HD];    // h hi bf16
static __device__ unsigned short d_hl[(size_t)NN * HD];    // h lo bf16
static __device__ unsigned short d_wih_h[H3 * HD], d_wih_l[H3 * HD];
static __device__ unsigned short d_whh_h[H3 * HD], d_whh_l[H3 * HD];
static __device__ int   d_cnt[NN];
static __device__ int   d_rowptr[NN + 1];
static __device__ int   d_cur[NN];
static __device__ int   d_csrc[ET];
static __device__ int   d_mcnt[MBLOCKS];

__device__ __forceinline__ uint32_t s2u(const void* p) {
    uint32_t a;
    asm("{ .reg .u64 t; cvta.to.shared.u64 t, %1; cvt.u32.u64 %0, t; }"
        : "=r"(a) : "l"(p));
    return a;
}

__device__ __forceinline__ void split_bf16(float v, unsigned short& hi,
                                           unsigned short& lo) {
    __nv_bfloat16 h = __float2bfloat16_rn(v);
    float rem = v - __bfloat162float(h);
    __nv_bfloat16 l = __float2bfloat16_rn(rem);
    hi = __bfloat16_as_ushort(h);
    lo = __bfloat16_as_ushort(l);
}

__device__ __forceinline__ void ldsm4(uint32_t* r, uint32_t addr) {
    asm volatile("ldmatrix.sync.aligned.m8n8.x4.shared.b16 {%0,%1,%2,%3}, [%4];"
                 : "=r"(r[0]), "=r"(r[1]), "=r"(r[2]), "=r"(r[3]) : "r"(addr));
}
__device__ __forceinline__ void mma16816(float* c, const uint32_t* a,
                                         uint32_t b0, uint32_t b1) {
    asm volatile(
        "mma.sync.aligned.m16n8k16.row.col.f32.bf16.bf16.f32 "
        "{%0,%1,%2,%3}, {%4,%5,%6,%7}, {%8,%9}, {%0,%1,%2,%3};"
        : "+f"(c[0]), "+f"(c[1]), "+f"(c[2]), "+f"(c[3])
        : "r"(a[0]), "r"(a[1]), "r"(a[2]), "r"(a[3]), "r"(b0), "r"(b1));
}

// ---------------- CSR build ----------------
__global__ void k_hist(const int* __restrict__ ei) {
    int idx = blockIdx.x * blockDim.x + threadIdx.x;
    if (idx < NE) {
        atomicAdd(&d_cnt[ei[NE + idx]], 1);
    } else if (idx < ET) {
        atomicAdd(&d_cnt[idx - NE], 1);
    }
}

__global__ void k_scan() {
    __shared__ int sh[1024];
    __shared__ int carry;
    int tid = threadIdx.x;
    if (tid == 0) carry = 0;
    __syncthreads();
    for (int base = 0; base < NN; base += 1024) {
        int v = (base + tid < NN) ? d_cnt[base + tid] : 0;
        sh[tid] = v;
        __syncthreads();
        for (int off = 1; off < 1024; off <<= 1) {
            int t2 = (tid >= off) ? sh[tid - off] : 0;
            __syncthreads();
            sh[tid] += t2;
            __syncthreads();
        }
        int inc = sh[tid];
        int ex = inc - v;
        if (base + tid < NN) {
            d_rowptr[base + tid] = carry + ex;
            d_cur[base + tid] = carry + ex;
        }
        int tot = sh[1023];
        __syncthreads();
        if (tid == 0) carry += tot;
        __syncthreads();
    }
    if (tid == 0) d_rowptr[NN] = carry;
}

__global__ void k_scatter(const int* __restrict__ ei) {
    int idx = blockIdx.x * blockDim.x + threadIdx.x;
    if (idx < NE) {
        int s = ei[idx];
        int d = ei[NE + idx];
        int p = atomicAdd(&d_cur[d], 1);
        d_csrc[p] = s;
    } else if (idx < ET) {
        int i = idx - NE;
        int p = atomicAdd(&d_cur[i], 1);
        d_csrc[p] = i;
    }
}

// ---------------- weight split to hi/lo bf16 ----------------
__global__ void k_wconv(const float* __restrict__ Wih,
                        const float* __restrict__ Whh) {
    int idx = blockIdx.x * blockDim.x + threadIdx.x;
    if (idx < H3 * HD) {
        split_bf16(Wih[idx], d_wih_h[idx], d_wih_l[idx]);
        split_bf16(Whh[idx], d_whh_h[idx], d_whh_l[idx]);
    }
}

// ---------------- xp = x_t @ Wg + attention dots ----------------
__global__ void k_xp(const float* __restrict__ x_t,
                     const float* __restrict__ Wg,
                     const float* __restrict__ att_s,
                     const float* __restrict__ att_d) {
    __shared__ float sWg[FIN * HD];
    __shared__ float sas[HD], sad[HD];
    __shared__ float sx[2][FIN];
    __shared__ float red_s[2][4], red_d[2][4];
    int tid = threadIdx.x;  // 256
    for (int i = tid; i < FIN * HD; i += 256) sWg[i] = Wg[i];
    if (tid < HD) { sas[tid] = att_s[tid]; sad[tid] = att_d[tid]; }
    int row = blockIdx.x * 2 + (tid / HD);
    int lr = tid / HD;
    int j = tid % HD;
    if (j < FIN && row < NN) sx[lr][j] = x_t[(size_t)row * FIN + j];
    __syncthreads();
    if (row >= NN) return;
    float acc = 0.f;
#pragma unroll
    for (int k = 0; k < FIN; k++) acc += sx[lr][k] * sWg[k * HD + j];
    d_xp[(size_t)row * HD + j] = acc;
    float vs = acc * sas[j];
    float vd = acc * sad[j];
#pragma unroll
    for (int o = 16; o > 0; o >>= 1) {
        vs += __shfl_down_sync(0xffffffffu, vs, o);
        vd += __shfl_down_sync(0xffffffffu, vd, o);
    }
    int lane = tid & 31;
    int w = (tid >> 5) & 3;
    if (lane == 0) { red_s[lr][w] = vs; red_d[lr][w] = vd; }
    __syncthreads();
    if (j == 0) {
        d_as[row] = red_s[lr][0] + red_s[lr][1] + red_s[lr][2] + red_s[lr][3];
        d_ad[row] = red_d[lr][0] + red_d[lr][1] + red_d[lr][2] + red_d[lr][3];
    }
}

// ---------------- GAT aggregate: warp/row softmax (scores bounded) -----------
__global__ void k_gat(const float* __restrict__ bias_g) {
    int warp = threadIdx.x >> 5, lane = threadIdx.x & 31;
    int row = blockIdx.x * 8 + warp;
    if (row >= NN) return;
    float ad = d_ad[row];
    int r0 = d_rowptr[row], r1 = d_rowptr[row + 1];
    float s = 0.f;
    float ax = 0.f, ay = 0.f, az = 0.f, aw = 0.f;
    int c = lane * 4;
    for (int e = r0; e < r1; e++) {
        int src = d_csrc[e];
        float ev = d_as[src] + ad;
        ev = (ev >= 0.f) ? ev : NEG * ev;
        float w = expf(ev);
        s += w;
        float4 v = *(const float4*)(d_xp + (size_t)src * HD + c);
        ax += w * v.x;
        ay += w * v.y;
        az += w * v.z;
        aw += w * v.w;
    }
    float inv = 1.f / s;
    float4 b = *(const float4*)(bias_g + c);
    float4 o;
    o.x = fmaxf(ax * inv + b.x, 0.f);
    o.y = fmaxf(ay * inv + b.y, 0.f);
    o.z = fmaxf(az * inv + b.z, 0.f);
    o.w = fmaxf(aw * inv + b.w, 0.f);
    unsigned short h0, h1, h2, h3, l0, l1, l2, l3;
    split_bf16(o.x, h0, l0);
    split_bf16(o.y, h1, l1);
    split_bf16(o.z, h2, l2);
    split_bf16(o.w, h3, l3);
    size_t off = (size_t)row * HD + c;
    uint2 ph = make_uint2((uint32_t)h0 | ((uint32_t)h1 << 16),
                          (uint32_t)h2 | ((uint32_t)h3 << 16));
    uint2 pl = make_uint2((uint32_t)l0 | ((uint32_t)l1 << 16),
                          (uint32_t)l2 | ((uint32_t)l3 << 16));
    *(uint2*)(d_sph + off) = ph;
    *(uint2*)(d_spl + off) = pl;
}

// ---- merged HMMA GEMMs (z=0: gi, z=1: gh) + last-CTA fused GRU --------------
#define TSTRIDE 272                 // padded row stride in bytes
#define TILE_B (128 * TSTRIDE)      // 34816
#define SM_BIAS 0
#define SM_T0 512
#define MMA_SMEM (512 + 4 * TILE_B)

__global__ void __launch_bounds__(256, 1)
k_mma(const uint4* __restrict__ A0h, const uint4* __restrict__ A0l,
      const uint4* __restrict__ B0h, const uint4* __restrict__ B0l,
      const float* __restrict__ bias0,
      const uint4* __restrict__ A1h, const uint4* __restrict__ A1l,
      const uint4* __restrict__ B1h, const uint4* __restrict__ B1l,
      const float* __restrict__ bias1, int M) {
    extern __shared__ char smem[];
    uint32_t sb = s2u(smem);
    int tid = threadIdx.x, wid = tid >> 5, lane = tid & 31;
    int m0 = blockIdx.x * 128, cb = blockIdx.y;
    int gz = blockIdx.z;
    const uint4* Ah = gz ? A1h : A0h;
    const uint4* Al = gz ? A1l : A0l;
    const uint4* Bh = gz ? B1h : B0h;
    const uint4* Bl = gz ? B1l : B0l;
    const float* bias = gz ? bias1 : bias0;
    float* C = gz ? d_gh : d_gi;

    if (tid < 128) ((float*)(smem + SM_BIAS))[tid] = bias[cb * 128 + tid];

    for (int idx = tid; idx < 2048; idx += 256) {
        int r = idx >> 4, q = idx & 15;
        int gm = m0 + r;
        uint4 vh = make_uint4(0, 0, 0, 0), vl = make_uint4(0, 0, 0, 0);
        if (gm < M) {
            vh = Ah[(size_t)gm * 16 + q];
            vl = Al[(size_t)gm * 16 + q];
        }
        char* dst = smem + SM_T0 + r * TSTRIDE + q * 16;
        *(uint4*)dst = vh;
        *(uint4*)(dst + TILE_B) = vl;
        int gb = cb * 128 + r;
        uint4 wh = Bh[(size_t)gb * 16 + q];
        uint4 wl = Bl[(size_t)gb * 16 + q];
        *(uint4*)(dst + 2 * TILE_B) = wh;
        *(uint4*)(dst + 3 * TILE_B) = wl;
    }
    __syncthreads();

    int warp_m = (wid >> 2) * 64;
    int warp_n = (wid & 3) * 32;

    float acc[4][4][4];
#pragma unroll
    for (int i = 0; i < 4; i++)
#pragma unroll
        for (int j = 0; j < 4; j++)
#pragma unroll
            for (int k = 0; k < 4; k++) acc[i][j][k] = 0.f;

    uint32_t aAddr[4], bAddr[2];
    {
        int rowA = (lane & 7) + ((lane >> 3) & 1) * 8;
        int kofA = ((lane >> 4) & 1) * 16;
#pragma unroll
        for (int mi = 0; mi < 4; mi++)
            aAddr[mi] = sb + SM_T0 +
                        (warp_m + mi * 16 + rowA) * TSTRIDE + kofA;
        int rowB = (lane & 7) + ((lane >> 4) & 1) * 8;
        int kofB = ((lane >> 3) & 1) * 16;
#pragma unroll
        for (int p = 0; p < 2; p++)
            bAddr[p] = sb + SM_T0 + 2 * TILE_B +
                       (warp_n + p * 16 + rowB) * TSTRIDE + kofB;
    }

#pragma unroll
    for (int ks = 0; ks < 8; ks++) {
        uint32_t ah[4][4], al[4][4], bh[2][4], bl[2][4];
#pragma unroll
        for (int mi = 0; mi < 4; mi++) {
            uint32_t ad = aAddr[mi] + ks * 32;
            ldsm4(ah[mi], ad);
            ldsm4(al[mi], ad + TILE_B);
        }
#pragma unroll
        for (int p = 0; p < 2; p++) {
            uint32_t bd = bAddr[p] + ks * 32;
            ldsm4(bh[p], bd);
            ldsm4(bl[p], bd + TILE_B);
        }
#pragma unroll
        for (int mi = 0; mi < 4; mi++) {
#pragma unroll
            for (int p = 0; p < 2; p++) {
#pragma unroll
                for (int sub = 0; sub < 2; sub++) {
                    float* c = acc[mi][p * 2 + sub];
                    uint32_t b0 = bh[p][sub * 2 + 0], b1 = bh[p][sub * 2 + 1];
                    mma16816(c, ah[mi], b0, b1);
                    mma16816(c, al[mi], b0, b1);
                    mma16816(c, ah[mi], bl[p][sub * 2 + 0],
                             bl[p][sub * 2 + 1]);
                }
            }
        }
    }

    const float* sbias = (const float*)(smem + SM_BIAS);
    int trow = lane >> 2, tcol = (lane & 3) * 2;
#pragma unroll
    for (int mi = 0; mi < 4; mi++) {
        int gm0 = m0 + warp_m + mi * 16 + trow;
#pragma unroll
        for (int nj = 0; nj < 4; nj++) {
            int nc = warp_n + nj * 8 + tcol;
            int gc = cb * 128 + nc;
            float b0 = sbias[nc], b1 = sbias[nc + 1];
            if (gm0 < M) {
                float2 o = make_float2(acc[mi][nj][0] + b0,
                                       acc[mi][nj][1] + b1);
                *(float2*)(C + (size_t)gm0 * H3 + gc) = o;
            }
            if (gm0 + 8 < M) {
                float2 o = make_float2(acc[mi][nj][2] + b0,
                                       acc[mi][nj][3] + b1);
                *(float2*)(C + (size_t)(gm0 + 8) * H3 + gc) = o;
            }
        }
    }

    // ---- last-CTA-done fused GRU for rows m0..m0+127 ----
    __shared__ int is_last;
    __threadfence();
    __syncthreads();
    if (tid == 0) {
        int old = atomicAdd(&d_mcnt[blockIdx.x], 1);
        is_last = (old == 5);
        if (old == 5) d_mcnt[blockIdx.x] = 0;   // reset for next launch
    }
    __syncthreads();
    if (!is_last) return;
    __threadfence();

    for (int i = tid; i < 128 * (HD / 4); i += 256) {
        int r = i >> 5, q4 = i & 31;
        int gm = m0 + r;
        if (gm >= M) continue;
        int j4 = q4 * 4;
        const float* gi = d_gi + (size_t)gm * H3 + j4;
        const float* gh = d_gh + (size_t)gm * H3 + j4;
        float4 gir = __ldcs((const float4*)gi);
        float4 giz = __ldcs((const float4*)(gi + HD));
        float4 gin = __ldcs((const float4*)(gi + 2 * HD));
        float4 ghr = __ldcs((const float4*)gh);
        float4 ghz = __ldcs((const float4*)(gh + HD));
        float4 ghn = __ldcs((const float4*)(gh + 2 * HD));
        size_t hoff = (size_t)gm * HD + j4;
        float4 h = *(const float4*)(d_h + hoff);
        float4 o;
#define GRU1(c)                                                   \
        {                                                         \
            float rr = 1.f / (1.f + expf(-(gir.c + ghr.c)));      \
            float zz = 1.f / (1.f + expf(-(giz.c + ghz.c)));      \
            float nn = tanhf(gin.c + rr * ghn.c);                 \
            o.c = (1.f - zz) * nn + zz * h.c;                     \
        }
        GRU1(x) GRU1(y) GRU1(z) GRU1(w)
#undef GRU1
        *(float4*)(d_h + hoff) = o;
        unsigned short h0, h1, h2, h3, l0, l1, l2, l3;
        split_bf16(o.x, h0, l0);
        split_bf16(o.y, h1, l1);
        split_bf16(o.z, h2, l2);
        split_bf16(o.w, h3, l3);
        uint2 ph = make_uint2((uint32_t)h0 | ((uint32_t)h1 << 16),
                              (uint32_t)h2 | ((uint32_t)h3 << 16));
        uint2 pl = make_uint2((uint32_t)l0 | ((uint32_t)l1 << 16),
                              (uint32_t)l2 | ((uint32_t)l3 << 16));
        *(uint2*)(d_hh + hoff) = ph;
        *(uint2*)(d_hl + hoff) = pl;
    }
}

// ---------------- final fc ----------------
__global__ void k_fc(const float* __restrict__ Wfc,
                     const float* __restrict__ bfc,
                     float* __restrict__ out) {
    int warp = threadIdx.x >> 5, lane = threadIdx.x & 31;
    int row = blockIdx.x * 8 + warp;
    if (row >= NN) return;
    float4 hv = *(const float4*)(d_h + (size_t)row * HD + lane * 4);
    float4 wv = *(const float4*)(Wfc + lane * 4);
    float v = hv.x * wv.x + hv.y * wv.y + hv.z * wv.z + hv.w * wv.w;
#pragma unroll
    for (int o = 16; o > 0; o >>= 1) v += __shfl_down_sync(0xffffffffu, v, o);
    if (lane == 0) out[row] = v + bfc[0];
}

// ---------------- launch ----------------
extern "C" void kernel_launch(void* const* d_in, const int* in_sizes, int n_in,
                              void* d_out, int out_size) {
    const float* x_seq   = (const float*)d_in[0];
    const int*   ei      = (const int*)d_in[1];
    const float* Wg      = (const float*)d_in[2];
    const float* att_src = (const float*)d_in[3];
    const float* att_dst = (const float*)d_in[4];
    const float* bias_g  = (const float*)d_in[5];
    const float* W_ih    = (const float*)d_in[6];
    const float* W_hh    = (const float*)d_in[7];
    const float* b_ih    = (const float*)d_in[8];
    const float* b_hh    = (const float*)d_in[9];
    const float* W_fc    = (const float*)d_in[10];
    const float* b_fc    = (const float*)d_in[11];
    float* out = (float*)d_out;

    void *p_cnt, *p_h, *p_hh, *p_hl, *p_sph, *p_spl, *p_mcnt;
    void *p_wih_h, *p_wih_l, *p_whh_h, *p_whh_l;
    cudaGetSymbolAddress(&p_cnt, d_cnt);
    cudaGetSymbolAddress(&p_h, d_h);
    cudaGetSymbolAddress(&p_hh, d_hh);
    cudaGetSymbolAddress(&p_hl, d_hl);
    cudaGetSymbolAddress(&p_sph, d_sph);
    cudaGetSymbolAddress(&p_spl, d_spl);
    cudaGetSymbolAddress(&p_mcnt, d_mcnt);
    cudaGetSymbolAddress(&p_wih_h, d_wih_h);
    cudaGetSymbolAddress(&p_wih_l, d_wih_l);
    cudaGetSymbolAddress(&p_whh_h, d_whh_h);
    cudaGetSymbolAddress(&p_whh_l, d_whh_l);

    cudaFuncSetAttribute(k_mma, cudaFuncAttributeMaxDynamicSharedMemorySize,
                         MMA_SMEM);

    cudaMemsetAsync(p_cnt, 0, NN * sizeof(int));
    cudaMemsetAsync(p_mcnt, 0, MBLOCKS * sizeof(int));
    cudaMemsetAsync(p_h, 0, (size_t)NN * HD * sizeof(float));
    cudaMemsetAsync(p_hh, 0, (size_t)NN * HD * sizeof(unsigned short));
    cudaMemsetAsync(p_hl, 0, (size_t)NN * HD * sizeof(unsigned short));

    k_wconv<<<(H3 * HD + 255) / 256, 256>>>(W_ih, W_hh);
    k_hist<<<(ET + 255) / 256, 256>>>(ei);
    k_scan<<<1, 1024>>>();
    k_scatter<<<(ET + 255) / 256, 256>>>(ei);

    dim3 mgrid(MBLOCKS, 3, 2);
    for (int t = 0; t < SEQL; t++) {
        k_xp<<<(NN + 1) / 2, 256>>>(x_seq + (size_t)t * NN * FIN, Wg,
                                    att_src, att_dst);
        k_gat<<<(NN + 7) / 8, 256>>>(bias_g);
        k_mma<<<mgrid, 256, MMA_SMEM>>>(
            (const uint4*)p_sph, (const uint4*)p_spl,
            (const uint4*)p_wih_h, (const uint4*)p_wih_l, b_ih,
            (const uint4*)p_hh, (const uint4*)p_hl,
            (const uint4*)p_whh_h, (const uint4*)p_whh_l, b_hh,
            NN);
    }

    k_fc<<<(NN + 7) / 8, 256>>>(W_fc, b_fc, out);
}

// round 16
// speedup vs baseline: 1.2362x; 1.2362x over previous
#include <cuda_runtime.h>
#include <cuda_bf16.h>
#include <math.h>
#include <cstdint>

#define NN 50000
#define SEQL 52
#define FIN 16
#define HD 128
#define H3 384
#define NE 800000
#define ET (NE + NN)
#define NEG 0.2f

// ---------------- static scratch ----------------
static __device__ float d_xp[(size_t)NN * HD];
static __device__ float d_as[NN];
static __device__ float d_ad[NN];
static __device__ unsigned short d_sph[(size_t)NN * HD];   // spatial hi bf16
static __device__ unsigned short d_spl[(size_t)NN * HD];   // spatial lo bf16
static __device__ float d_gi[(size_t)NN * H3];
static __device__ float d_gh[(size_t)NN * H3];
static __device__ float d_h[(size_t)NN * HD];
static __device__ unsigned short d_hh[(size_t)NN * HD];    // h hi bf16
static __device__ unsigned short d_hl[(size_t)NN * HD];    // h lo bf16
static __device__ unsigned short d_wih_h[H3 * HD], d_wih_l[H3 * HD];
static __device__ unsigned short d_whh_h[H3 * HD], d_whh_l[H3 * HD];
static __device__ int   d_cnt[NN];
static __device__ int   d_rowptr[NN + 1];
static __device__ int   d_cur[NN];
static __device__ int   d_csrc[ET];

__device__ __forceinline__ uint32_t s2u(const void* p) {
    uint32_t a;
    asm("{ .reg .u64 t; cvta.to.shared.u64 t, %1; cvt.u32.u64 %0, t; }"
        : "=r"(a) : "l"(p));
    return a;
}

__device__ __forceinline__ void split_bf16(float v, unsigned short& hi,
                                           unsigned short& lo) {
    __nv_bfloat16 h = __float2bfloat16_rn(v);
    float rem = v - __bfloat162float(h);
    __nv_bfloat16 l = __float2bfloat16_rn(rem);
    hi = __bfloat16_as_ushort(h);
    lo = __bfloat16_as_ushort(l);
}

__device__ __forceinline__ void ldsm4(uint32_t* r, uint32_t addr) {
    asm volatile("ldmatrix.sync.aligned.m8n8.x4.shared.b16 {%0,%1,%2,%3}, [%4];"
                 : "=r"(r[0]), "=r"(r[1]), "=r"(r[2]), "=r"(r[3]) : "r"(addr));
}
__device__ __forceinline__ void mma16816(float* c, const uint32_t* a,
                                         uint32_t b0, uint32_t b1) {
    asm volatile(
        "mma.sync.aligned.m16n8k16.row.col.f32.bf16.bf16.f32 "
        "{%0,%1,%2,%3}, {%4,%5,%6,%7}, {%8,%9}, {%0,%1,%2,%3};"
        : "+f"(c[0]), "+f"(c[1]), "+f"(c[2]), "+f"(c[3])
        : "r"(a[0]), "r"(a[1]), "r"(a[2]), "r"(a[3]), "r"(b0), "r"(b1));
}

// ---------------- CSR build ----------------
__global__ void k_hist(const int* __restrict__ ei) {
    int idx = blockIdx.x * blockDim.x + threadIdx.x;
    if (idx < NE) {
        atomicAdd(&d_cnt[ei[NE + idx]], 1);
    } else if (idx < ET) {
        atomicAdd(&d_cnt[idx - NE], 1);
    }
}

__global__ void k_scan() {
    __shared__ int sh[1024];
    __shared__ int carry;
    int tid = threadIdx.x;
    if (tid == 0) carry = 0;
    __syncthreads();
    for (int base = 0; base < NN; base += 1024) {
        int v = (base + tid < NN) ? d_cnt[base + tid] : 0;
        sh[tid] = v;
        __syncthreads();
        for (int off = 1; off < 1024; off <<= 1) {
            int t2 = (tid >= off) ? sh[tid - off] : 0;
            __syncthreads();
            sh[tid] += t2;
            __syncthreads();
        }
        int inc = sh[tid];
        int ex = inc - v;
        if (base + tid < NN) {
            d_rowptr[base + tid] = carry + ex;
            d_cur[base + tid] = carry + ex;
        }
        int tot = sh[1023];
        __syncthreads();
        if (tid == 0) carry += tot;
        __syncthreads();
    }
    if (tid == 0) d_rowptr[NN] = carry;
}

__global__ void k_scatter(const int* __restrict__ ei) {
    int idx = blockIdx.x * blockDim.x + threadIdx.x;
    if (idx < NE) {
        int s = ei[idx];
        int d = ei[NE + idx];
        int p = atomicAdd(&d_cur[d], 1);
        d_csrc[p] = s;
    } else if (idx < ET) {
        int i = idx - NE;
        int p = atomicAdd(&d_cur[i], 1);
        d_csrc[p] = i;
    }
}

// ---------------- weight split to hi/lo bf16 ----------------
__global__ void k_wconv(const float* __restrict__ Wih,
                        const float* __restrict__ Whh) {
    int idx = blockIdx.x * blockDim.x + threadIdx.x;
    if (idx < H3 * HD) {
        split_bf16(Wih[idx], d_wih_h[idx], d_wih_l[idx]);
        split_bf16(Whh[idx], d_whh_h[idx], d_whh_l[idx]);
    }
}

// ---------------- xp = x_t @ Wg + attention dots ----------------
__global__ void k_xp(const float* __restrict__ x_t,
                     const float* __restrict__ Wg,
                     const float* __restrict__ att_s,
                     const float* __restrict__ att_d) {
    __shared__ float sWg[FIN * HD];
    __shared__ float sas[HD], sad[HD];
    __shared__ float sx[2][FIN];
    __shared__ float red_s[2][4], red_d[2][4];
    int tid = threadIdx.x;  // 256
    for (int i = tid; i < FIN * HD; i += 256) sWg[i] = Wg[i];
    if (tid < HD) { sas[tid] = att_s[tid]; sad[tid] = att_d[tid]; }
    int row = blockIdx.x * 2 + (tid / HD);
    int lr = tid / HD;
    int j = tid % HD;
    if (j < FIN && row < NN) sx[lr][j] = x_t[(size_t)row * FIN + j];
    __syncthreads();
    if (row >= NN) return;
    float acc = 0.f;
#pragma unroll
    for (int k = 0; k < FIN; k++) acc += sx[lr][k] * sWg[k * HD + j];
    d_xp[(size_t)row * HD + j] = acc;
    float vs = acc * sas[j];
    float vd = acc * sad[j];
#pragma unroll
    for (int o = 16; o > 0; o >>= 1) {
        vs += __shfl_down_sync(0xffffffffu, vs, o);
        vd += __shfl_down_sync(0xffffffffu, vd, o);
    }
    int lane = tid & 31;
    int w = (tid >> 5) & 3;
    if (lane == 0) { red_s[lr][w] = vs; red_d[lr][w] = vd; }
    __syncthreads();
    if (j == 0) {
        d_as[row] = red_s[lr][0] + red_s[lr][1] + red_s[lr][2] + red_s[lr][3];
        d_ad[row] = red_d[lr][0] + red_d[lr][1] + red_d[lr][2] + red_d[lr][3];
    }
}

// ---------------- GAT aggregate: warp/row softmax (scores bounded) -----------
__global__ void k_gat(const float* __restrict__ bias_g) {
    int warp = threadIdx.x >> 5, lane = threadIdx.x & 31;
    int row = blockIdx.x * 8 + warp;
    if (row >= NN) return;
    float ad = d_ad[row];
    int r0 = d_rowptr[row], r1 = d_rowptr[row + 1];
    float s = 0.f;
    float ax = 0.f, ay = 0.f, az = 0.f, aw = 0.f;
    int c = lane * 4;
    for (int e = r0; e < r1; e++) {
        int src = d_csrc[e];
        float ev = d_as[src] + ad;
        ev = (ev >= 0.f) ? ev : NEG * ev;
        float w = expf(ev);
        s += w;
        float4 v = *(const float4*)(d_xp + (size_t)src * HD + c);
        ax += w * v.x;
        ay += w * v.y;
        az += w * v.z;
        aw += w * v.w;
    }
    float inv = 1.f / s;
    float4 b = *(const float4*)(bias_g + c);
    float4 o;
    o.x = fmaxf(ax * inv + b.x, 0.f);
    o.y = fmaxf(ay * inv + b.y, 0.f);
    o.z = fmaxf(az * inv + b.z, 0.f);
    o.w = fmaxf(aw * inv + b.w, 0.f);
    unsigned short h0, h1, h2, h3, l0, l1, l2, l3;
    split_bf16(o.x, h0, l0);
    split_bf16(o.y, h1, l1);
    split_bf16(o.z, h2, l2);
    split_bf16(o.w, h3, l3);
    size_t off = (size_t)row * HD + c;
    uint2 ph = make_uint2((uint32_t)h0 | ((uint32_t)h1 << 16),
                          (uint32_t)h2 | ((uint32_t)h3 << 16));
    uint2 pl = make_uint2((uint32_t)l0 | ((uint32_t)l1 << 16),
                          (uint32_t)l2 | ((uint32_t)l3 << 16));
    *(uint2*)(d_sph + off) = ph;
    *(uint2*)(d_spl + off) = pl;
}

// ---- merged HMMA split-bf16 GEMMs, 64-row tiles, 2 CTAs/SM ------------------
// z=0: gi = sp @ Wih^T + b_ih ; z=1: gh = h @ Whh^T + b_hh
#define TSTRIDE 272                  // padded row stride in bytes
#define A_TILE (64 * TSTRIDE)        // 17408
#define B_TILE (128 * TSTRIDE)       // 34816
#define SM_BIAS 0
#define SM_AH 512
#define SM_AL (SM_AH + A_TILE)
#define SM_BH (SM_AH + 2 * A_TILE)
#define SM_BL (SM_BH + B_TILE)
#define MMA_SMEM (SM_BH + 2 * B_TILE)   // 105264

__global__ void __launch_bounds__(256, 2)
k_mma(const uint4* __restrict__ A0h, const uint4* __restrict__ A0l,
      const uint4* __restrict__ B0h, const uint4* __restrict__ B0l,
      const float* __restrict__ bias0, float* __restrict__ C0,
      const uint4* __restrict__ A1h, const uint4* __restrict__ A1l,
      const uint4* __restrict__ B1h, const uint4* __restrict__ B1l,
      const float* __restrict__ bias1, float* __restrict__ C1, int M) {
    extern __shared__ char smem[];
    uint32_t sb = s2u(smem);
    int tid = threadIdx.x, wid = tid >> 5, lane = tid & 31;
    int m0 = blockIdx.x * 64, cb = blockIdx.y;
    int gz = blockIdx.z;
    const uint4* Ah = gz ? A1h : A0h;
    const uint4* Al = gz ? A1l : A0l;
    const uint4* Bh = gz ? B1h : B0h;
    const uint4* Bl = gz ? B1l : B0l;
    const float* bias = gz ? bias1 : bias0;
    float* C = gz ? C1 : C0;

    if (tid < 128) ((float*)(smem + SM_BIAS))[tid] = bias[cb * 128 + tid];

    // A tiles: 64 rows x 128 bf16, hi+lo
    for (int idx = tid; idx < 1024; idx += 256) {
        int r = idx >> 4, q = idx & 15;
        int gm = m0 + r;
        uint4 vh = make_uint4(0, 0, 0, 0), vl = vh;
        if (gm < M) {
            size_t go = (size_t)gm * 16 + q;
            vh = Ah[go];
            vl = Al[go];
        }
        char* dst = smem + r * TSTRIDE + q * 16;
        *(uint4*)(dst + SM_AH) = vh;
        *(uint4*)(dst + SM_AL) = vl;
    }
    // B tiles: 128 rows (gate cols cb*128..) x 128 bf16, hi+lo
    for (int idx = tid; idx < 2048; idx += 256) {
        int r = idx >> 4, q = idx & 15;
        size_t go = (size_t)(cb * 128 + r) * 16 + q;
        char* dst = smem + r * TSTRIDE + q * 16;
        *(uint4*)(dst + SM_BH) = Bh[go];
        *(uint4*)(dst + SM_BL) = Bl[go];
    }
    __syncthreads();

    // warp tiling: 2 (M) x 4 (N) warps; warp tile 32x32
    int warp_m = (wid >> 2) * 32;
    int warp_n = (wid & 3) * 32;

    float acc[2][4][4];
#pragma unroll
    for (int i = 0; i < 2; i++)
#pragma unroll
        for (int j = 0; j < 4; j++)
#pragma unroll
            for (int k = 0; k < 4; k++) acc[i][j][k] = 0.f;

    uint32_t aAddr[2], bAddr[2];
    {
        int rowA = (lane & 7) + ((lane >> 3) & 1) * 8;
        int kofA = ((lane >> 4) & 1) * 16;
#pragma unroll
        for (int mi = 0; mi < 2; mi++)
            aAddr[mi] = sb + SM_AH + (warp_m + mi * 16 + rowA) * TSTRIDE + kofA;
        int rowB = (lane & 7) + ((lane >> 4) & 1) * 8;
        int kofB = ((lane >> 3) & 1) * 16;
#pragma unroll
        for (int p = 0; p < 2; p++)
            bAddr[p] = sb + SM_BH + (warp_n + p * 16 + rowB) * TSTRIDE + kofB;
    }

#pragma unroll
    for (int ks = 0; ks < 8; ks++) {
        uint32_t ah[2][4], al[2][4], bh[2][4], bl[2][4];
#pragma unroll
        for (int mi = 0; mi < 2; mi++) {
            uint32_t ad = aAddr[mi] + ks * 32;
            ldsm4(ah[mi], ad);
            ldsm4(al[mi], ad + A_TILE);
        }
#pragma unroll
        for (int p = 0; p < 2; p++) {
            uint32_t bd = bAddr[p] + ks * 32;
            ldsm4(bh[p], bd);
            ldsm4(bl[p], bd + B_TILE);
        }
#pragma unroll
        for (int mi = 0; mi < 2; mi++) {
#pragma unroll
            for (int p = 0; p < 2; p++) {
#pragma unroll
                for (int sub = 0; sub < 2; sub++) {
                    float* c = acc[mi][p * 2 + sub];
                    uint32_t b0 = bh[p][sub * 2 + 0], b1 = bh[p][sub * 2 + 1];
                    mma16816(c, ah[mi], b0, b1);
                    mma16816(c, al[mi], b0, b1);
                    mma16816(c, ah[mi], bl[p][sub * 2 + 0],
                             bl[p][sub * 2 + 1]);
                }
            }
        }
    }

    const float* sbias = (const float*)(smem + SM_BIAS);
    int trow = lane >> 2, tcol = (lane & 3) * 2;
#pragma unroll
    for (int mi = 0; mi < 2; mi++) {
        int gm0 = m0 + warp_m + mi * 16 + trow;
#pragma unroll
        for (int nj = 0; nj < 4; nj++) {
            int nc = warp_n + nj * 8 + tcol;
            int gc = cb * 128 + nc;
            float b0 = sbias[nc], b1 = sbias[nc + 1];
            if (gm0 < M) {
                float2 o = make_float2(acc[mi][nj][0] + b0,
                                       acc[mi][nj][1] + b1);
                *(float2*)(C + (size_t)gm0 * H3 + gc) = o;
            }
            if (gm0 + 8 < M) {
                float2 o = make_float2(acc[mi][nj][2] + b0,
                                       acc[mi][nj][3] + b1);
                *(float2*)(C + (size_t)(gm0 + 8) * H3 + gc) = o;
            }
        }
    }
}

// ---------------- GRU elementwise update; streaming gi/gh reads --------------
__global__ void k_gru() {
    int idx = blockIdx.x * blockDim.x + threadIdx.x;   // over NN*HD/4
    if (idx >= NN * HD / 4) return;
    int i = idx / (HD / 4), j4 = (idx % (HD / 4)) * 4;
    const float* gi = d_gi + (size_t)i * H3 + j4;
    const float* gh = d_gh + (size_t)i * H3 + j4;
    float4 gir = __ldcs((const float4*)gi);
    float4 giz = __ldcs((const float4*)(gi + HD));
    float4 gin = __ldcs((const float4*)(gi + 2 * HD));
    float4 ghr = __ldcs((const float4*)gh);
    float4 ghz = __ldcs((const float4*)(gh + HD));
    float4 ghn = __ldcs((const float4*)(gh + 2 * HD));
    size_t hoff = (size_t)i * HD + j4;
    float4 h = *(const float4*)(d_h + hoff);
    float4 o;
#define GRU1(c)                                                   \
    {                                                             \
        float r = 1.f / (1.f + expf(-(gir.c + ghr.c)));           \
        float z = 1.f / (1.f + expf(-(giz.c + ghz.c)));           \
        float n = tanhf(gin.c + r * ghn.c);                       \
        o.c = (1.f - z) * n + z * h.c;                            \
    }
    GRU1(x) GRU1(y) GRU1(z) GRU1(w)
#undef GRU1
    *(float4*)(d_h + hoff) = o;
    unsigned short h0, h1, h2, h3, l0, l1, l2, l3;
    split_bf16(o.x, h0, l0);
    split_bf16(o.y, h1, l1);
    split_bf16(o.z, h2, l2);
    split_bf16(o.w, h3, l3);
    uint2 ph = make_uint2((uint32_t)h0 | ((uint32_t)h1 << 16),
                          (uint32_t)h2 | ((uint32_t)h3 << 16));
    uint2 pl = make_uint2((uint32_t)l0 | ((uint32_t)l1 << 16),
                          (uint32_t)l2 | ((uint32_t)l3 << 16));
    *(uint2*)(d_hh + hoff) = ph;
    *(uint2*)(d_hl + hoff) = pl;
}

// ---------------- final fc ----------------
__global__ void k_fc(const float* __restrict__ Wfc,
                     const float* __restrict__ bfc,
                     float* __restrict__ out) {
    int warp = threadIdx.x >> 5, lane = threadIdx.x & 31;
    int row = blockIdx.x * 8 + warp;
    if (row >= NN) return;
    float4 hv = *(const float4*)(d_h + (size_t)row * HD + lane * 4);
    float4 wv = *(const float4*)(Wfc + lane * 4);
    float v = hv.x * wv.x + hv.y * wv.y + hv.z * wv.z + hv.w * wv.w;
#pragma unroll
    for (int o = 16; o > 0; o >>= 1) v += __shfl_down_sync(0xffffffffu, v, o);
    if (lane == 0) out[row] = v + bfc[0];
}

// ---------------- launch ----------------
extern "C" void kernel_launch(void* const* d_in, const int* in_sizes, int n_in,
                              void* d_out, int out_size) {
    const float* x_seq   = (const float*)d_in[0];
    const int*   ei      = (const int*)d_in[1];
    const float* Wg      = (const float*)d_in[2];
    const float* att_src = (const float*)d_in[3];
    const float* att_dst = (const float*)d_in[4];
    const float* bias_g  = (const float*)d_in[5];
    const float* W_ih    = (const float*)d_in[6];
    const float* W_hh    = (const float*)d_in[7];
    const float* b_ih    = (const float*)d_in[8];
    const float* b_hh    = (const float*)d_in[9];
    const float* W_fc    = (const float*)d_in[10];
    const float* b_fc    = (const float*)d_in[11];
    float* out = (float*)d_out;

    void *p_cnt, *p_h, *p_hh, *p_hl, *p_sph, *p_spl, *p_gi, *p_gh;
    void *p_wih_h, *p_wih_l, *p_whh_h, *p_whh_l;
    cudaGetSymbolAddress(&p_cnt, d_cnt);
    cudaGetSymbolAddress(&p_h, d_h);
    cudaGetSymbolAddress(&p_hh, d_hh);
    cudaGetSymbolAddress(&p_hl, d_hl);
    cudaGetSymbolAddress(&p_sph, d_sph);
    cudaGetSymbolAddress(&p_spl, d_spl);
    cudaGetSymbolAddress(&p_gi, d_gi);
    cudaGetSymbolAddress(&p_gh, d_gh);
    cudaGetSymbolAddress(&p_wih_h, d_wih_h);
    cudaGetSymbolAddress(&p_wih_l, d_wih_l);
    cudaGetSymbolAddress(&p_whh_h, d_whh_h);
    cudaGetSymbolAddress(&p_whh_l, d_whh_l);

    cudaFuncSetAttribute(k_mma, cudaFuncAttributeMaxDynamicSharedMemorySize,
                         MMA_SMEM);

    cudaMemsetAsync(p_cnt, 0, NN * sizeof(int));
    cudaMemsetAsync(p_h, 0, (size_t)NN * HD * sizeof(float));
    cudaMemsetAsync(p_hh, 0, (size_t)NN * HD * sizeof(unsigned short));
    cudaMemsetAsync(p_hl, 0, (size_t)NN * HD * sizeof(unsigned short));

    k_wconv<<<(H3 * HD + 255) / 256, 256>>>(W_ih, W_hh);
    k_hist<<<(ET + 255) / 256, 256>>>(ei);
    k_scan<<<1, 1024>>>();
    k_scatter<<<(ET + 255) / 256, 256>>>(ei);

    dim3 mgrid((NN + 63) / 64, 3, 2);
    for (int t = 0; t < SEQL; t++) {
        k_xp<<<(NN + 1) / 2, 256>>>(x_seq + (size_t)t * NN * FIN, Wg,
                                    att_src, att_dst);
        k_gat<<<(NN + 7) / 8, 256>>>(bias_g);
        k_mma<<<mgrid, 256, MMA_SMEM>>>(
            (const uint4*)p_sph, (const uint4*)p_spl,
            (const uint4*)p_wih_h, (const uint4*)p_wih_l, b_ih, (float*)p_gi,
            (const uint4*)p_hh, (const uint4*)p_hl,
            (const uint4*)p_whh_h, (const uint4*)p_whh_l, b_hh, (float*)p_gh,
            NN);
        k_gru<<<(NN * HD / 4 + 255) / 256, 256>>>();
    }

    k_fc<<<(NN + 7) / 8, 256>>>(W_fc, b_fc, out);
}

// round 17
// speedup vs baseline: 1.4548x; 1.1769x over previous
#include <cuda_runtime.h>
#include <cuda_bf16.h>
#include <math.h>
#include <cstdint>

#define NN 50000
#define SEQL 52
#define FIN 16
#define HD 128
#define H3 384
#define NE 800000
#define ET (NE + NN)
#define NEG 0.2f

// ---------------- static scratch ----------------
static __device__ float d_xp[(size_t)NN * HD];
static __device__ float d_as[NN];
static __device__ float d_ad[NN];
static __device__ unsigned short d_sph[(size_t)NN * HD];   // spatial hi bf16
static __device__ unsigned short d_spl[(size_t)NN * HD];   // spatial lo bf16
static __device__ float d_gi[(size_t)NN * H3];
static __device__ float d_gh[(size_t)NN * H3];
static __device__ unsigned short d_hh[(size_t)NN * HD];    // h hi bf16
static __device__ unsigned short d_hl[(size_t)NN * HD];    // h lo bf16
static __device__ unsigned short d_wih_h[H3 * HD], d_wih_l[H3 * HD];
static __device__ unsigned short d_whh_h[H3 * HD], d_whh_l[H3 * HD];
static __device__ int   d_cnt[NN];
static __device__ int   d_rowptr[NN + 1];
static __device__ int   d_cur[NN];
static __device__ int   d_csrc[ET];

__device__ __forceinline__ uint32_t s2u(const void* p) {
    uint32_t a;
    asm("{ .reg .u64 t; cvta.to.shared.u64 t, %1; cvt.u32.u64 %0, t; }"
        : "=r"(a) : "l"(p));
    return a;
}

__device__ __forceinline__ void split_bf16(float v, unsigned short& hi,
                                           unsigned short& lo) {
    __nv_bfloat16 h = __float2bfloat16_rn(v);
    float rem = v - __bfloat162float(h);
    __nv_bfloat16 l = __float2bfloat16_rn(rem);
    hi = __bfloat16_as_ushort(h);
    lo = __bfloat16_as_ushort(l);
}

__device__ __forceinline__ float bf2f(unsigned short u) {
    return __bfloat162float(__ushort_as_bfloat16(u));
}

__device__ __forceinline__ void ldsm4(uint32_t* r, uint32_t addr) {
    asm volatile("ldmatrix.sync.aligned.m8n8.x4.shared.b16 {%0,%1,%2,%3}, [%4];"
                 : "=r"(r[0]), "=r"(r[1]), "=r"(r[2]), "=r"(r[3]) : "r"(addr));
}
__device__ __forceinline__ void mma16816(float* c, const uint32_t* a,
                                         uint32_t b0, uint32_t b1) {
    asm volatile(
        "mma.sync.aligned.m16n8k16.row.col.f32.bf16.bf16.f32 "
        "{%0,%1,%2,%3}, {%4,%5,%6,%7}, {%8,%9}, {%0,%1,%2,%3};"
        : "+f"(c[0]), "+f"(c[1]), "+f"(c[2]), "+f"(c[3])
        : "r"(a[0]), "r"(a[1]), "r"(a[2]), "r"(a[3]), "r"(b0), "r"(b1));
}

// ---------------- CSR build ----------------
__global__ void k_hist(const int* __restrict__ ei) {
    int idx = blockIdx.x * blockDim.x + threadIdx.x;
    if (idx < NE) {
        atomicAdd(&d_cnt[ei[NE + idx]], 1);
    } else if (idx < ET) {
        atomicAdd(&d_cnt[idx - NE], 1);
    }
}

__global__ void k_scan() {
    __shared__ int sh[1024];
    __shared__ int carry;
    int tid = threadIdx.x;
    if (tid == 0) carry = 0;
    __syncthreads();
    for (int base = 0; base < NN; base += 1024) {
        int v = (base + tid < NN) ? d_cnt[base + tid] : 0;
        sh[tid] = v;
        __syncthreads();
        for (int off = 1; off < 1024; off <<= 1) {
            int t2 = (tid >= off) ? sh[tid - off] : 0;
            __syncthreads();
            sh[tid] += t2;
            __syncthreads();
        }
        int inc = sh[tid];
        int ex = inc - v;
        if (base + tid < NN) {
            d_rowptr[base + tid] = carry + ex;
            d_cur[base + tid] = carry + ex;
        }
        int tot = sh[1023];
        __syncthreads();
        if (tid == 0) carry += tot;
        __syncthreads();
    }
    if (tid == 0) d_rowptr[NN] = carry;
}

__global__ void k_scatter(const int* __restrict__ ei) {
    int idx = blockIdx.x * blockDim.x + threadIdx.x;
    if (idx < NE) {
        int s = ei[idx];
        int d = ei[NE + idx];
        int p = atomicAdd(&d_cur[d], 1);
        d_csrc[p] = s;
    } else if (idx < ET) {
        int i = idx - NE;
        int p = atomicAdd(&d_cur[i], 1);
        d_csrc[p] = i;
    }
}

// ---------------- weight split to hi/lo bf16 ----------------
__global__ void k_wconv(const float* __restrict__ Wih,
                        const float* __restrict__ Whh) {
    int idx = blockIdx.x * blockDim.x + threadIdx.x;
    if (idx < H3 * HD) {
        split_bf16(Wih[idx], d_wih_h[idx], d_wih_l[idx]);
        split_bf16(Whh[idx], d_whh_h[idx], d_whh_l[idx]);
    }
}

// ---------------- xp = x_t @ Wg + attention dots (16 rows/block) -------------
__global__ void k_xp(const float* __restrict__ x_t,
                     const float* __restrict__ Wg,
                     const float* __restrict__ att_s,
                     const float* __restrict__ att_d) {
    __shared__ float sWg[FIN * HD];
    int tid = threadIdx.x, wid = tid >> 5, lane = tid & 31;
    for (int i = tid; i < FIN * HD; i += 256) sWg[i] = Wg[i];
    __syncthreads();
    float4 as4 = *(const float4*)(att_s + lane * 4);
    float4 ad4 = *(const float4*)(att_d + lane * 4);
#pragma unroll
    for (int rr = 0; rr < 2; rr++) {
        int row = blockIdx.x * 16 + wid * 2 + rr;
        if (row >= NN) break;
        float xv = 0.f;
        if (lane < FIN) xv = x_t[(size_t)row * FIN + lane];
        float a0 = 0.f, a1 = 0.f, a2 = 0.f, a3 = 0.f;
#pragma unroll
        for (int k = 0; k < FIN; k++) {
            float xk = __shfl_sync(0xffffffffu, xv, k);
            const float* wr = &sWg[k * HD + lane * 4];
            a0 += xk * wr[0];
            a1 += xk * wr[1];
            a2 += xk * wr[2];
            a3 += xk * wr[3];
        }
        *(float4*)(d_xp + (size_t)row * HD + lane * 4) =
            make_float4(a0, a1, a2, a3);
        float vs = a0 * as4.x + a1 * as4.y + a2 * as4.z + a3 * as4.w;
        float vd = a0 * ad4.x + a1 * ad4.y + a2 * ad4.z + a3 * ad4.w;
#pragma unroll
        for (int o = 16; o > 0; o >>= 1) {
            vs += __shfl_down_sync(0xffffffffu, vs, o);
            vd += __shfl_down_sync(0xffffffffu, vd, o);
        }
        if (lane == 0) { d_as[row] = vs; d_ad[row] = vd; }
    }
}

// ---------------- GAT aggregate: warp/row softmax (scores bounded) -----------
__global__ void k_gat(const float* __restrict__ bias_g) {
    int warp = threadIdx.x >> 5, lane = threadIdx.x & 31;
    int row = blockIdx.x * 8 + warp;
    if (row >= NN) return;
    float ad = d_ad[row];
    int r0 = d_rowptr[row], r1 = d_rowptr[row + 1];
    float s = 0.f;
    float ax = 0.f, ay = 0.f, az = 0.f, aw = 0.f;
    int c = lane * 4;
    for (int e = r0; e < r1; e++) {
        int src = d_csrc[e];
        float ev = d_as[src] + ad;
        ev = (ev >= 0.f) ? ev : NEG * ev;
        float w = expf(ev);
        s += w;
        float4 v = *(const float4*)(d_xp + (size_t)src * HD + c);
        ax += w * v.x;
        ay += w * v.y;
        az += w * v.z;
        aw += w * v.w;
    }
    float inv = 1.f / s;
    float4 b = *(const float4*)(bias_g + c);
    float4 o;
    o.x = fmaxf(ax * inv + b.x, 0.f);
    o.y = fmaxf(ay * inv + b.y, 0.f);
    o.z = fmaxf(az * inv + b.z, 0.f);
    o.w = fmaxf(aw * inv + b.w, 0.f);
    unsigned short h0, h1, h2, h3, l0, l1, l2, l3;
    split_bf16(o.x, h0, l0);
    split_bf16(o.y, h1, l1);
    split_bf16(o.z, h2, l2);
    split_bf16(o.w, h3, l3);
    size_t off = (size_t)row * HD + c;
    uint2 ph = make_uint2((uint32_t)h0 | ((uint32_t)h1 << 16),
                          (uint32_t)h2 | ((uint32_t)h3 << 16));
    uint2 pl = make_uint2((uint32_t)l0 | ((uint32_t)l1 << 16),
                          (uint32_t)l2 | ((uint32_t)l3 << 16));
    *(uint2*)(d_sph + off) = ph;
    *(uint2*)(d_spl + off) = pl;
}

// ---- merged HMMA split-bf16 GEMMs, 64-row tiles, 2 CTAs/SM ------------------
// z=0: gi = sp @ Wih^T + b_ih ; z=1: gh = h @ Whh^T + b_hh
#define TSTRIDE 272                  // padded row stride in bytes
#define A_TILE (64 * TSTRIDE)        // 17408
#define B_TILE (128 * TSTRIDE)       // 34816
#define SM_BIAS 0
#define SM_AH 512
#define SM_AL (SM_AH + A_TILE)
#define SM_BH (SM_AH + 2 * A_TILE)
#define SM_BL (SM_BH + B_TILE)
#define MMA_SMEM (SM_BH + 2 * B_TILE)   // 105264

__global__ void __launch_bounds__(256, 2)
k_mma(const uint4* __restrict__ A0h, const uint4* __restrict__ A0l,
      const uint4* __restrict__ B0h, const uint4* __restrict__ B0l,
      const float* __restrict__ bias0, float* __restrict__ C0,
      const uint4* __restrict__ A1h, const uint4* __restrict__ A1l,
      const uint4* __restrict__ B1h, const uint4* __restrict__ B1l,
      const float* __restrict__ bias1, float* __restrict__ C1, int M) {
    extern __shared__ char smem[];
    uint32_t sb = s2u(smem);
    int tid = threadIdx.x, wid = tid >> 5, lane = tid & 31;
    int m0 = blockIdx.x * 64, cb = blockIdx.y;
    int gz = blockIdx.z;
    const uint4* Ah = gz ? A1h : A0h;
    const uint4* Al = gz ? A1l : A0l;
    const uint4* Bh = gz ? B1h : B0h;
    const uint4* Bl = gz ? B1l : B0l;
    const float* bias = gz ? bias1 : bias0;
    float* C = gz ? C1 : C0;

    if (tid < 128) ((float*)(smem + SM_BIAS))[tid] = bias[cb * 128 + tid];

    // A tiles: 64 rows x 128 bf16, hi+lo
    for (int idx = tid; idx < 1024; idx += 256) {
        int r = idx >> 4, q = idx & 15;
        int gm = m0 + r;
        uint4 vh = make_uint4(0, 0, 0, 0), vl = vh;
        if (gm < M) {
            size_t go = (size_t)gm * 16 + q;
            vh = Ah[go];
            vl = Al[go];
        }
        char* dst = smem + r * TSTRIDE + q * 16;
        *(uint4*)(dst + SM_AH) = vh;
        *(uint4*)(dst + SM_AL) = vl;
    }
    // B tiles: 128 rows (gate cols cb*128..) x 128 bf16, hi+lo
    for (int idx = tid; idx < 2048; idx += 256) {
        int r = idx >> 4, q = idx & 15;
        size_t go = (size_t)(cb * 128 + r) * 16 + q;
        char* dst = smem + r * TSTRIDE + q * 16;
        *(uint4*)(dst + SM_BH) = Bh[go];
        *(uint4*)(dst + SM_BL) = Bl[go];
    }
    __syncthreads();

    // warp tiling: 2 (M) x 4 (N) warps; warp tile 32x32
    int warp_m = (wid >> 2) * 32;
    int warp_n = (wid & 3) * 32;

    float acc[2][4][4];
#pragma unroll
    for (int i = 0; i < 2; i++)
#pragma unroll
        for (int j = 0; j < 4; j++)
#pragma unroll
            for (int k = 0; k < 4; k++) acc[i][j][k] = 0.f;

    uint32_t aAddr[2], bAddr[2];
    {
        int rowA = (lane & 7) + ((lane >> 3) & 1) * 8;
        int kofA = ((lane >> 4) & 1) * 16;
#pragma unroll
        for (int mi = 0; mi < 2; mi++)
            aAddr[mi] = sb + SM_AH + (warp_m + mi * 16 + rowA) * TSTRIDE + kofA;
        int rowB = (lane & 7) + ((lane >> 4) & 1) * 8;
        int kofB = ((lane >> 3) & 1) * 16;
#pragma unroll
        for (int p = 0; p < 2; p++)
            bAddr[p] = sb + SM_BH + (warp_n + p * 16 + rowB) * TSTRIDE + kofB;
    }

#pragma unroll
    for (int ks = 0; ks < 8; ks++) {
        uint32_t ah[2][4], al[2][4], bh[2][4], bl[2][4];
#pragma unroll
        for (int mi = 0; mi < 2; mi++) {
            uint32_t ad = aAddr[mi] + ks * 32;
            ldsm4(ah[mi], ad);
            ldsm4(al[mi], ad + A_TILE);
        }
#pragma unroll
        for (int p = 0; p < 2; p++) {
            uint32_t bd = bAddr[p] + ks * 32;
            ldsm4(bh[p], bd);
            ldsm4(bl[p], bd + B_TILE);
        }
#pragma unroll
        for (int mi = 0; mi < 2; mi++) {
#pragma unroll
            for (int p = 0; p < 2; p++) {
#pragma unroll
                for (int sub = 0; sub < 2; sub++) {
                    float* c = acc[mi][p * 2 + sub];
                    uint32_t b0 = bh[p][sub * 2 + 0], b1 = bh[p][sub * 2 + 1];
                    mma16816(c, ah[mi], b0, b1);
                    mma16816(c, al[mi], b0, b1);
                    mma16816(c, ah[mi], bl[p][sub * 2 + 0],
                             bl[p][sub * 2 + 1]);
                }
            }
        }
    }

    const float* sbias = (const float*)(smem + SM_BIAS);
    int trow = lane >> 2, tcol = (lane & 3) * 2;
#pragma unroll
    for (int mi = 0; mi < 2; mi++) {
        int gm0 = m0 + warp_m + mi * 16 + trow;
#pragma unroll
        for (int nj = 0; nj < 4; nj++) {
            int nc = warp_n + nj * 8 + tcol;
            int gc = cb * 128 + nc;
            float b0 = sbias[nc], b1 = sbias[nc + 1];
            if (gm0 < M) {
                float2 o = make_float2(acc[mi][nj][0] + b0,
                                       acc[mi][nj][1] + b1);
                *(float2*)(C + (size_t)gm0 * H3 + gc) = o;
            }
            if (gm0 + 8 < M) {
                float2 o = make_float2(acc[mi][nj][2] + b0,
                                       acc[mi][nj][3] + b1);
                *(float2*)(C + (size_t)(gm0 + 8) * H3 + gc) = o;
            }
        }
    }
}

// ---------------- GRU elementwise update; h kept as hi/lo bf16 only ----------
__global__ void k_gru() {
    int idx = blockIdx.x * blockDim.x + threadIdx.x;   // over NN*HD/4
    if (idx >= NN * HD / 4) return;
    int i = idx / (HD / 4), j4 = (idx % (HD / 4)) * 4;
    const float* gi = d_gi + (size_t)i * H3 + j4;
    const float* gh = d_gh + (size_t)i * H3 + j4;
    float4 gir = __ldcs((const float4*)gi);
    float4 giz = __ldcs((const float4*)(gi + HD));
    float4 gin = __ldcs((const float4*)(gi + 2 * HD));
    float4 ghr = __ldcs((const float4*)gh);
    float4 ghz = __ldcs((const float4*)(gh + HD));
    float4 ghn = __ldcs((const float4*)(gh + 2 * HD));
    size_t hoff = (size_t)i * HD + j4;
    uint2 phv = *(const uint2*)(d_hh + hoff);
    uint2 plv = *(const uint2*)(d_hl + hoff);
    float4 h;
    h.x = bf2f(phv.x & 0xffff) + bf2f(plv.x & 0xffff);
    h.y = bf2f(phv.x >> 16) + bf2f(plv.x >> 16);
    h.z = bf2f(phv.y & 0xffff) + bf2f(plv.y & 0xffff);
    h.w = bf2f(phv.y >> 16) + bf2f(plv.y >> 16);
    float4 o;
#define GRU1(c)                                                   \
    {                                                             \
        float r = 1.f / (1.f + expf(-(gir.c + ghr.c)));           \
        float z = 1.f / (1.f + expf(-(giz.c + ghz.c)));           \
        float n = tanhf(gin.c + r * ghn.c);                       \
        o.c = (1.f - z) * n + z * h.c;                            \
    }
    GRU1(x) GRU1(y) GRU1(z) GRU1(w)
#undef GRU1
    unsigned short h0, h1, h2, h3, l0, l1, l2, l3;
    split_bf16(o.x, h0, l0);
    split_bf16(o.y, h1, l1);
    split_bf16(o.z, h2, l2);
    split_bf16(o.w, h3, l3);
    uint2 ph = make_uint2((uint32_t)h0 | ((uint32_t)h1 << 16),
                          (uint32_t)h2 | ((uint32_t)h3 << 16));
    uint2 pl = make_uint2((uint32_t)l0 | ((uint32_t)l1 << 16),
                          (uint32_t)l2 | ((uint32_t)l3 << 16));
    *(uint2*)(d_hh + hoff) = ph;
    *(uint2*)(d_hl + hoff) = pl;
}

// ---------------- final fc ----------------
__global__ void k_fc(const float* __restrict__ Wfc,
                     const float* __restrict__ bfc,
                     float* __restrict__ out) {
    int warp = threadIdx.x >> 5, lane = threadIdx.x & 31;
    int row = blockIdx.x * 8 + warp;
    if (row >= NN) return;
    size_t hoff = (size_t)row * HD + lane * 4;
    uint2 phv = *(const uint2*)(d_hh + hoff);
    uint2 plv = *(const uint2*)(d_hl + hoff);
    float4 hv;
    hv.x = bf2f(phv.x & 0xffff) + bf2f(plv.x & 0xffff);
    hv.y = bf2f(phv.x >> 16) + bf2f(plv.x >> 16);
    hv.z = bf2f(phv.y & 0xffff) + bf2f(plv.y & 0xffff);
    hv.w = bf2f(phv.y >> 16) + bf2f(plv.y >> 16);
    float4 wv = *(const float4*)(Wfc + lane * 4);
    float v = hv.x * wv.x + hv.y * wv.y + hv.z * wv.z + hv.w * wv.w;
#pragma unroll
    for (int o = 16; o > 0; o >>= 1) v += __shfl_down_sync(0xffffffffu, v, o);
    if (lane == 0) out[row] = v + bfc[0];
}

// ---------------- launch ----------------
extern "C" void kernel_launch(void* const* d_in, const int* in_sizes, int n_in,
                              void* d_out, int out_size) {
    const float* x_seq   = (const float*)d_in[0];
    const int*   ei      = (const int*)d_in[1];
    const float* Wg      = (const float*)d_in[2];
    const float* att_src = (const float*)d_in[3];
    const float* att_dst = (const float*)d_in[4];
    const float* bias_g  = (const float*)d_in[5];
    const float* W_ih    = (const float*)d_in[6];
    const float* W_hh    = (const float*)d_in[7];
    const float* b_ih    = (const float*)d_in[8];
    const float* b_hh    = (const float*)d_in[9];
    const float* W_fc    = (const float*)d_in[10];
    const float* b_fc    = (const float*)d_in[11];
    float* out = (float*)d_out;

    void *p_cnt, *p_hh, *p_hl, *p_sph, *p_spl, *p_gi, *p_gh;
    void *p_wih_h, *p_wih_l, *p_whh_h, *p_whh_l;
    cudaGetSymbolAddress(&p_cnt, d_cnt);
    cudaGetSymbolAddress(&p_hh, d_hh);
    cudaGetSymbolAddress(&p_hl, d_hl);
    cudaGetSymbolAddress(&p_sph, d_sph);
    cudaGetSymbolAddress(&p_spl, d_spl);
    cudaGetSymbolAddress(&p_gi, d_gi);
    cudaGetSymbolAddress(&p_gh, d_gh);
    cudaGetSymbolAddress(&p_wih_h, d_wih_h);
    cudaGetSymbolAddress(&p_wih_l, d_wih_l);
    cudaGetSymbolAddress(&p_whh_h, d_whh_h);
    cudaGetSymbolAddress(&p_whh_l, d_whh_l);

    cudaFuncSetAttribute(k_mma, cudaFuncAttributeMaxDynamicSharedMemorySize,
                         MMA_SMEM);

    cudaMemsetAsync(p_cnt, 0, NN * sizeof(int));
    cudaMemsetAsync(p_hh, 0, (size_t)NN * HD * sizeof(unsigned short));
    cudaMemsetAsync(p_hl, 0, (size_t)NN * HD * sizeof(unsigned short));

    k_wconv<<<(H3 * HD + 255) / 256, 256>>>(W_ih, W_hh);
    k_hist<<<(ET + 255) / 256, 256>>>(ei);
    k_scan<<<1, 1024>>>();
    k_scatter<<<(ET + 255) / 256, 256>>>(ei);

    dim3 mgrid((NN + 63) / 64, 3, 2);
    for (int t = 0; t < SEQL; t++) {
        k_xp<<<(NN + 15) / 16, 256>>>(x_seq + (size_t)t * NN * FIN, Wg,
                                      att_src, att_dst);
        k_gat<<<(NN + 7) / 8, 256>>>(bias_g);
        k_mma<<<mgrid, 256, MMA_SMEM>>>(
            (const uint4*)p_sph, (const uint4*)p_spl,
            (const uint4*)p_wih_h, (const uint4*)p_wih_l, b_ih, (float*)p_gi,
            (const uint4*)p_hh, (const uint4*)p_hl,
            (const uint4*)p_whh_h, (const uint4*)p_whh_l, b_hh, (float*)p_gh,
            NN);
        k_gru<<<(NN * HD / 4 + 255) / 256, 256>>>();
    }

    k_fc<<<(NN + 7) / 8, 256>>>(W_fc, b_fc, out);
}